// round 14
// baseline (speedup 1.0000x reference)
#include <cuda_runtime.h>
#include <cuda_bf16.h>
#include <cuda_fp16.h>
#include <cstdint>

#define SEQ       128
#define BATCH     64
#define EMBED     512
#define HDIM      1024
#define NG        4096
#define TSTEPS    127
#define SEL_START 65
#define SEL_COUNT 62
#define MPAD      8192
#define NCTA      128

// ---------------- device scratch ----------------
__device__ __half g_Xh[MPAD * EMBED];          // fp16 embeddings (t-major)
__device__ __half g_Wih[NG * EMBED];           // fp16 w_ih, gate-interleaved rows
__device__ __half g_Whh[NG * HDIM];            // fp16 w_hh, gate-interleaved rows
__device__ float g_bsum[NG];
__device__ float g_P[TSTEPS * BATCH * NG];     // preacts, gate-interleaved cols
__device__ __half g_h2[2 * BATCH * HDIM];      // ping-pong h (fp16)
__device__ unsigned g_flag[2][64];             // [batch-half][col-group] step flags
__device__ int g_is64;

// ---------------- smem layout for lstm_persist (bytes) ----------------
#define OFF_H    0        // [32][1032] fp16 = 66048 (also W staging pre-loop)
#define OFF_PART 66048    // [4][32][68] f32 = 34816
#define OFF_PS   100864   // 2 x [32][64] f32 = 16384
#define SMEM_PERSIST 117248

// ---------------- gemm_pre smem: 3 stages x (A[128][72] + B[128][72]) fp16
#define GP_STAGE 36864
#define GP_SMEM  110592

// ---------------- helpers ----------------
__device__ __forceinline__ void mma16816h(float* c, const uint32_t* a, const uint32_t* b) {
    asm volatile(
        "mma.sync.aligned.m16n8k16.row.col.f32.f16.f16.f32 "
        "{%0,%1,%2,%3}, {%4,%5,%6,%7}, {%8,%9}, {%0,%1,%2,%3};\n"
        : "+f"(c[0]), "+f"(c[1]), "+f"(c[2]), "+f"(c[3])
        : "r"(a[0]), "r"(a[1]), "r"(a[2]), "r"(a[3]), "r"(b[0]), "r"(b[1]));
}
__device__ __forceinline__ void ldsm4(uint32_t* r, uint32_t saddr) {
    asm volatile("ldmatrix.sync.aligned.m8n8.x4.shared.b16 {%0,%1,%2,%3}, [%4];"
        : "=r"(r[0]), "=r"(r[1]), "=r"(r[2]), "=r"(r[3]) : "r"(saddr));
}
__device__ __forceinline__ uint32_t sptr(const void* p) {
    return (uint32_t)__cvta_generic_to_shared(p);
}
__device__ __forceinline__ void cpa16(void* smem, const void* g) {
    uint32_t s = sptr(smem);
    asm volatile("cp.async.cg.shared.global [%0], [%1], 16;\n" :: "r"(s), "l"(g));
}
__device__ __forceinline__ void cpa_commit() { asm volatile("cp.async.commit_group;\n"); }
__device__ __forceinline__ void cpa_wait2()  { asm volatile("cp.async.wait_group 2;\n"); }
__device__ __forceinline__ void cpa_wait1()  { asm volatile("cp.async.wait_group 1;\n"); }
__device__ __forceinline__ void cpa_wait0()  { asm volatile("cp.async.wait_group 0;\n"); }
__device__ __forceinline__ void ldv4(const void* p, unsigned* v) {
    asm volatile("ld.volatile.global.v4.u32 {%0,%1,%2,%3}, [%4];"
        : "=r"(v[0]), "=r"(v[1]), "=r"(v[2]), "=r"(v[3]) : "l"(p));
}
__device__ __forceinline__ float ex2f(float x) {
    float y; asm("ex2.approx.f32 %0, %1;" : "=f"(y) : "f"(x)); return y;
}
__device__ __forceinline__ float rcpf(float x) {
    float y; asm("rcp.approx.f32 %0, %1;" : "=f"(y) : "f"(x)); return y;
}
#define L2E  1.4426950408889634f
#define L2E2 2.8853900817779268f

// ---------------- fused init (detect + h0 + out + flags) ----------------
__global__ void fused_init(const int* __restrict__ prob32, const float* __restrict__ h0,
                           float* __restrict__ out, const float* __restrict__ b_ans) {
    int bid = blockIdx.x;
    if (bid == 0) {
        __shared__ int any;
        if (threadIdx.x == 0) any = 0;
        __syncthreads();
        int local = 0;
        for (int i = 2 * threadIdx.x + 1; i < BATCH * SEQ; i += 2 * blockDim.x)
            local |= prob32[i];
        if (local) atomicOr(&any, 1);
        __syncthreads();
        if (threadIdx.x == 0) g_is64 = (any == 0) ? 1 : 0;
        if (threadIdx.x < 128) ((unsigned*)g_flag)[threadIdx.x] = 0u;
    } else if (bid <= 64) {
        int i = (bid - 1) * 1024 + threadIdx.x;
        g_h2[i] = __float2half_rn(h0[i]);
    } else {
        int i = (bid - 65) * 1024 + threadIdx.x;
        if (i < BATCH * SEL_COUNT) out[i] = b_ans[0];
    }
}

// ---------------- merged prep: gather + weight conversion ----------------
__global__ void prep_all(const void* __restrict__ prob, const float* __restrict__ table,
                         const float* __restrict__ w_ih, const float* __restrict__ w_hh,
                         const float* __restrict__ b_ih, const float* __restrict__ b_hh) {
    int bid = blockIdx.x;
    int tid = threadIdx.x;
    if (bid < NG) {                       // w_ih -> fp16 (gate-interleaved)
        int n = bid;
        int j = n >> 2, g = n & 3;
        int r = g * HDIM + j;
        if (tid < 128) {
            float4 v = ((const float4*)(w_ih + (size_t)r * EMBED))[tid];
            int o = n * EMBED + tid * 4;
            g_Wih[o + 0] = __float2half_rn(v.x);
            g_Wih[o + 1] = __float2half_rn(v.y);
            g_Wih[o + 2] = __float2half_rn(v.z);
            g_Wih[o + 3] = __float2half_rn(v.w);
        }
        if (tid == 0) g_bsum[n] = b_ih[r] + b_hh[r];
    } else if (bid < 2 * NG) {            // w_hh -> fp16 (gate-interleaved)
        int n = bid - NG;
        int j = n >> 2, g = n & 3;
        int r = g * HDIM + j;
        float4 v = ((const float4*)(w_hh + (size_t)r * HDIM))[tid];
        int o = n * HDIM + tid * 4;
        g_Whh[o + 0] = __float2half_rn(v.x);
        g_Whh[o + 1] = __float2half_rn(v.y);
        g_Whh[o + 2] = __float2half_rn(v.z);
        g_Whh[o + 3] = __float2half_rn(v.w);
    } else {                              // gather: 2 rows per block
        int row = (bid - 2 * NG) * 2 + (tid >> 7);
        if (row < TSTEPS * BATCH) {
            int t = row >> 6, b = row & 63;
            long long tok;
            if (g_is64) tok = ((const long long*)prob)[b * SEQ + t];
            else        tok = (long long)((const int*)prob)[b * SEQ + t];
            int lt = tid & 127;
            float4 v = ((const float4*)(table + (size_t)tok * EMBED))[lt];
            int o = row * EMBED + lt * 4;
            g_Xh[o + 0] = __float2half_rn(v.x);
            g_Xh[o + 1] = __float2half_rn(v.y);
            g_Xh[o + 2] = __float2half_rn(v.z);
            g_Xh[o + 3] = __float2half_rn(v.w);
        }
    }
}

// ---------------- pre-GEMM: P = Xh @ Wih^T + bsum  [8192x4096, K=512] -----
__global__ __launch_bounds__(256, 2)
void gemm_pre() {
    extern __shared__ char gsm[];
    const int tid = threadIdx.x, warp = tid >> 5, lane = tid & 31;
    const int gid = lane >> 2, kb = (lane & 3) << 1;
    const int m_off = (warp >> 2) << 6;   // 0,64
    const int n_off = (warp & 3) << 5;    // 0,32,64,96
    const int m0 = blockIdx.y << 7;
    const int n0 = blockIdx.x << 7;
    const int a_r = (lane & 7) + (lane & 8);
    const int a_c = (lane & 16) >> 1;
    const int b_r = (lane & 7) + ((lane & 16) >> 1);
    const int b_c = (lane & 8);

    float acc[4][4][4];
#pragma unroll
    for (int a = 0; a < 4; a++)
#pragma unroll
        for (int b = 0; b < 4; b++)
#pragma unroll
            for (int cc = 0; cc < 4; cc++) acc[a][b][cc] = 0.0f;

    auto load_stage = [&](int s, int k0) {
        char* base = gsm + s * GP_STAGE;
#pragma unroll
        for (int it = 0; it < 8; it++) {
            int op = it * 256 + tid;
            int r = (op & 1023) >> 3;
            int c = op & 7;
            if (op < 1024)
                cpa16(base + r * 144 + c * 16,
                      g_Xh + (size_t)(m0 + r) * EMBED + k0 + c * 8);
            else
                cpa16(base + 18432 + r * 144 + c * 16,
                      g_Wih + (size_t)(n0 + r) * EMBED + k0 + c * 8);
        }
        cpa_commit();
    };

    auto compute = [&](int s) {
        uint32_t sA = sptr(gsm + s * GP_STAGE);
        uint32_t sAo = sA + (uint32_t)((m_off + a_r) * 72 + a_c) * 2;
        uint32_t sBo = sA + 18432 + (uint32_t)((n_off + b_r) * 72 + b_c) * 2;
#pragma unroll
        for (int ks = 0; ks < 64; ks += 16) {
            uint32_t ah[4][4], bh4[2][4];
#pragma unroll
            for (int mf = 0; mf < 4; mf++)
                ldsm4(ah[mf], sAo + (uint32_t)(mf * 16 * 72 + ks) * 2);
#pragma unroll
            for (int nh = 0; nh < 2; nh++)
                ldsm4(bh4[nh], sBo + (uint32_t)(nh * 16 * 72 + ks) * 2);
#pragma unroll
            for (int nf = 0; nf < 4; nf++) {
                const uint32_t* bh = &bh4[nf >> 1][(nf & 1) * 2];
#pragma unroll
                for (int mf = 0; mf < 4; mf++)
                    mma16816h(acc[mf][nf], ah[mf], bh);
            }
        }
    };

    const int KT = EMBED / 64;   // 8
    load_stage(0, 0);
    load_stage(1, 64);
    for (int kt = 0; kt < KT; kt++) {
        if (kt < KT - 1) cpa_wait1(); else cpa_wait0();
        __syncthreads();
        if (kt + 2 < KT) load_stage((kt + 2) % 3, (kt + 2) * 64);
        compute(kt % 3);
    }

#pragma unroll
    for (int mf = 0; mf < 4; mf++)
#pragma unroll
        for (int nf = 0; nf < 4; nf++) {
            int row = m0 + m_off + mf * 16 + gid;
            int col = n0 + n_off + nf * 8 + kb;
            float b0 = g_bsum[col], b1 = g_bsum[col + 1];
            if (row < TSTEPS * BATCH) {
                g_P[(size_t)row * NG + col]     = acc[mf][nf][0] + b0;
                g_P[(size_t)row * NG + col + 1] = acc[mf][nf][1] + b1;
            }
            if (row + 8 < TSTEPS * BATCH) {
                g_P[(size_t)(row + 8) * NG + col]     = acc[mf][nf][2] + b0;
                g_P[(size_t)(row + 8) * NG + col + 1] = acc[mf][nf][3] + b1;
            }
        }
}

// ---------------- persistent recurrent kernel -----------------------------
// 128 CTAs = 64 col-groups x 2 batch-halves; 8 warps = 4 K-quarters x 2
// N-halves; weights register-resident; h load 2-chunk pipelined vs MMA;
// single-writer flag sync (no atomics); publish-early epilogue.
__global__ __launch_bounds__(256, 1)
void lstm_persist(const float* __restrict__ c0, const float* __restrict__ w_ans,
                  float* __restrict__ out) {
    extern __shared__ char smc[];
    const int tid = threadIdx.x, warp = tid >> 5, lane = tid & 31;
    const int gid = lane >> 2, kb = (lane & 3) << 1;
    const int kq = warp >> 1;             // 0..3 K quarter
    const int nh = warp & 1;              // 0..1 N half (32 cols)
    const int cg = blockIdx.x >> 1;       // column group 0..63
    const int bh = blockIdx.x & 1;        // batch half
    const int n0 = cg << 6;               // 64 gate cols
    const int j0 = cg << 4;               // 16 j's
    const int b0 = bh << 5;               // 32 batch rows
    const int a_r = (lane & 7) + (lane & 8);
    const int a_c = (lane & 16) >> 1;
    const int b_r = (lane & 7) + ((lane & 16) >> 1);
    const int b_c = (lane & 8);

    float* part = (float*)(smc + OFF_PART);   // [4][32][68]

    // ---- stage W (64 cols x 1024) through h region in two 32-col passes ----
    uint32_t Breg[16][8];
#pragma unroll
    for (int st = 0; st < 2; st++) {
#pragma unroll
        for (int it = 0; it < 16; it++) {
            int op = it * 256 + tid;          // 0..4095
            int r = op >> 7, c = op & 127;
            cpa16(smc + OFF_H + (size_t)r * 2064 + c * 16,
                  g_Whh + (size_t)(n0 + st * 32 + r) * HDIM + c * 8);
        }
        cpa_commit(); cpa_wait0();
        __syncthreads();
        if (nh == st) {
            uint32_t sW = sptr(smc + OFF_H) + (uint32_t)(b_r * 2064) + (uint32_t)b_c * 2;
#pragma unroll
            for (int kf = 0; kf < 16; kf++) {
                uint32_t koff = (uint32_t)(kq * 256 + kf * 16) * 2;
                ldsm4(&Breg[kf][0], sW + koff);
                ldsm4(&Breg[kf][4], sW + 16u * 2064 + koff);
            }
        }
        __syncthreads();
    }

    // ---- per-thread state in registers: c and w_ans for (b, jj) items ----
    float c_reg[2], was_reg[2];
#pragma unroll
    for (int half = 0; half < 2; half++) {
        int idx = tid + half * 256;
        int b = idx >> 4, jj = idx & 15;
        c_reg[half]   = c0[(size_t)(b0 + b) * HDIM + j0 + jj];
        was_reg[half] = w_ans[j0 + jj];
    }

    const uint32_t sAB = sptr(smc + OFF_H) + (uint32_t)(a_r * 2064) + (uint32_t)a_c * 2;
    const unsigned* myflags = &g_flag[bh][kq * 16];   // 16 flags, 64B aligned

    // P(0) prologue load into Ps buf 0
    {
#pragma unroll
        for (int it = 0; it < 2; it++) {
            int op = it * 256 + tid;          // 0..511
            int r = op >> 4, c = op & 15;
            cpa16(smc + OFF_PS + r * 256 + c * 16,
                  g_P + (size_t)(b0 + r) * NG + n0 + c * 4);
        }
        cpa_commit();
    }

    for (int t = 0; t < TSTEPS; t++) {
        const __half* hsrc = g_h2 + (size_t)(t & 1) * (BATCH * HDIM);
        __half* hdst = g_h2 + (size_t)((t + 1) & 1) * (BATCH * HDIM);

        // ---- wait: my 16 producers' flags >= t (single-writer, no atomics) ----
        if (lane == 0) {
            unsigned tgt = (unsigned)t;
            for (;;) {
                unsigned v[16];
                ldv4(myflags + 0,  v + 0);
                ldv4(myflags + 4,  v + 4);
                ldv4(myflags + 8,  v + 8);
                ldv4(myflags + 12, v + 12);
                unsigned mn = v[0];
#pragma unroll
                for (int i = 1; i < 16; i++) mn = min(mn, v[i]);
                if (mn >= tgt) break;
            }
            __threadfence();
        }
        __syncwarp();

        // ---- h quarter in 2 K-chunks (16 rows x 128 cols each per warp) ----
#pragma unroll
        for (int ck = 0; ck < 2; ck++) {
#pragma unroll
            for (int it = 0; it < 8; it++) {
                int idx = it * 32 + lane;         // 0..255
                int r = nh * 16 + (idx >> 4), ch = (idx & 15) + ck * 16;
                cpa16(smc + OFF_H + (size_t)r * 2064 + (size_t)(kq * 512 + ch * 16),
                      hsrc + (size_t)(b0 + r) * HDIM + kq * 256 + ch * 8);
            }
            cpa_commit();
        }
        // ---- prefetch P(t+1) last (consumed next step; stays in flight) ----
        {
            int tp = (t + 1 < TSTEPS) ? (t + 1) : 0;
#pragma unroll
            for (int it = 0; it < 2; it++) {
                int op = it * 256 + tid;
                int r = op >> 4, c = op & 15;
                cpa16(smc + OFF_PS + ((t + 1) & 1) * 8192 + r * 256 + c * 16,
                      g_P + ((size_t)tp * BATCH + b0 + r) * NG + n0 + c * 4);
            }
            cpa_commit();
        }

        float acc[2][4][4];
#pragma unroll
        for (int a = 0; a < 2; a++)
#pragma unroll
            for (int b = 0; b < 4; b++)
#pragma unroll
                for (int q = 0; q < 4; q++) acc[a][b][q] = 0.0f;

        // ---- chunk0 ready (also drains P(t) from last step) -> MMA kf 0..7
        cpa_wait2();
        asm volatile("bar.sync %0, 64;" :: "r"(1 + kq) : "memory");
#pragma unroll
        for (int kf = 0; kf < 8; kf++) {
            uint32_t koff = (uint32_t)(kq * 256 + kf * 16) * 2;
            uint32_t ah[2][4];
            ldsm4(ah[0], sAB + koff);
            ldsm4(ah[1], sAB + 16u * 2064 + koff);
#pragma unroll
            for (int mf = 0; mf < 2; mf++)
#pragma unroll
                for (int nf = 0; nf < 4; nf++)
                    mma16816h(acc[mf][nf], ah[mf], &Breg[kf][nf * 2]);
        }
        // ---- chunk1 ready -> MMA kf 8..15 (P(t+1) still in flight) ----
        cpa_wait1();
        asm volatile("bar.sync %0, 64;" :: "r"(1 + kq) : "memory");
#pragma unroll
        for (int kf = 8; kf < 16; kf++) {
            uint32_t koff = (uint32_t)(kq * 256 + kf * 16) * 2;
            uint32_t ah[2][4];
            ldsm4(ah[0], sAB + koff);
            ldsm4(ah[1], sAB + 16u * 2064 + koff);
#pragma unroll
            for (int mf = 0; mf < 2; mf++)
#pragma unroll
                for (int nf = 0; nf < 4; nf++)
                    mma16816h(acc[mf][nf], ah[mf], &Breg[kf][nf * 2]);
        }

        // ---- store K-partials: part[kq][row 0..31][col 0..63] ----
        {
            float* pk = part + kq * 2176;     // 32*68
#pragma unroll
            for (int mf = 0; mf < 2; mf++)
#pragma unroll
                for (int nf = 0; nf < 4; nf++) {
                    int col = nh * 32 + nf * 8 + kb;
                    int row = mf * 16 + gid;
                    *(float2*)(pk + row * 68 + col)       = make_float2(acc[mf][nf][0], acc[mf][nf][1]);
                    *(float2*)(pk + (row + 8) * 68 + col) = make_float2(acc[mf][nf][2], acc[mf][nf][3]);
                }
        }
        __syncthreads();

        // ---- reduce partials + cell; store h; stash answer-dot term ----
        const float* Ps = (const float*)(smc + OFF_PS + (t & 1) * 8192);
        float pstash[2];
#pragma unroll
        for (int half = 0; half < 2; half++) {
            int idx = tid + half * 256;
            int b = idx >> 4, jj = idx & 15;
            const float* pb = part + b * 68 + jj * 4;
            float4 s0 = *(const float4*)(pb);
            float4 s1 = *(const float4*)(pb + 2176);
            float4 s2 = *(const float4*)(pb + 4352);
            float4 s3 = *(const float4*)(pb + 6528);
            float4 pv = *(const float4*)(Ps + b * 64 + jj * 4);
            float gi = s0.x + s1.x + s2.x + s3.x + pv.x;
            float gf = s0.y + s1.y + s2.y + s3.y + pv.y;
            float gg = s0.z + s1.z + s2.z + s3.z + pv.z;
            float go = s0.w + s1.w + s2.w + s3.w + pv.w;
            gi = fminf(fmaxf(gi, -15.0f), 15.0f);
            gf = fminf(fmaxf(gf, -15.0f), 15.0f);
            gg = fminf(fmaxf(gg, -15.0f), 15.0f);
            go = fminf(fmaxf(go, -15.0f), 15.0f);
            float ei = ex2f(-gi * L2E);
            float ef = ex2f(-gf * L2E);
            float eo = ex2f(-go * L2E);
            float d1 = 1.0f + ei, d2 = 1.0f + ef, d3 = 1.0f + eo;
            float m12 = d1 * d2, m23 = d2 * d3, m13 = d1 * d3;
            float r = rcpf(m12 * d3);
            float si = r * m23, sf = r * m13, so = r * m12;
            float eg = ex2f(gg * L2E2);
            float tg = (eg - 1.0f) * rcpf(eg + 1.0f);
            float c = sf * c_reg[half] + si * tg;
            c_reg[half] = c;
            float ac = fminf(fmaxf(c * L2E2, -60.0f), 60.0f);
            float ec = ex2f(ac);
            float tc = (ec - 1.0f) * rcpf(ec + 1.0f);
            float h = so * tc;
            hdst[(size_t)(b0 + b) * HDIM + j0 + jj] = __float2half_rn(h);
            pstash[half] = h * was_reg[half];
        }

        // ---- publish h(t+1): fence, sync, single release store ----
        __threadfence();
        __syncthreads();
        if (tid == 0) {
            unsigned nv = (unsigned)(t + 1);
            asm volatile("st.release.gpu.global.u32 [%0], %1;"
                         :: "l"(&g_flag[bh][cg]), "r"(nv) : "memory");
        }

        if (t >= SEL_START) {
#pragma unroll
            for (int half = 0; half < 2; half++) {
                int idx = tid + half * 256;
                int b = idx >> 4;
                float p = pstash[half];
                p += __shfl_xor_sync(0xFFFFFFFFu, p, 8);
                p += __shfl_xor_sync(0xFFFFFFFFu, p, 4);
                p += __shfl_xor_sync(0xFFFFFFFFu, p, 2);
                p += __shfl_xor_sync(0xFFFFFFFFu, p, 1);
                if ((lane & 15) == 0)
                    atomicAdd(&out[(b0 + b) * SEL_COUNT + (t - SEL_START)], p);
            }
        }
    }
}

// ---------------- launch ----------------
extern "C" void kernel_launch(void* const* d_in, const int* in_sizes, int n_in,
                              void* d_out, int out_size) {
    (void)in_sizes; (void)n_in; (void)out_size;
    const void*  prob  = d_in[0];
    const float* table = (const float*)d_in[2];
    const float* w_ih  = (const float*)d_in[3];
    const float* w_hh  = (const float*)d_in[4];
    const float* b_ih  = (const float*)d_in[5];
    const float* b_hh  = (const float*)d_in[6];
    const float* w_ans = (const float*)d_in[7];
    const float* b_ans = (const float*)d_in[8];
    const float* h0    = (const float*)d_in[9];
    const float* c0    = (const float*)d_in[10];
    float* out = (float*)d_out;

    static bool inited = false;
    if (!inited) {
        cudaFuncSetAttribute(gemm_pre,     cudaFuncAttributeMaxDynamicSharedMemorySize, GP_SMEM);
        cudaFuncSetAttribute(lstm_persist, cudaFuncAttributeMaxDynamicSharedMemorySize, SMEM_PERSIST);
        inited = true;
    }

    fused_init<<<69, 1024>>>((const int*)prob, h0, out, b_ans);
    prep_all<<<2 * NG + (TSTEPS * BATCH + 1) / 2, 256>>>(prob, table, w_ih, w_hh, b_ih, b_hh);
    gemm_pre<<<dim3(NG / 128, MPAD / 128), 256, GP_SMEM>>>();
    lstm_persist<<<NCTA, 256, SMEM_PERSIST>>>(c0, w_ans, out);
}

// round 15
// speedup vs baseline: 2.3032x; 2.3032x over previous
#include <cuda_runtime.h>
#include <cuda_bf16.h>
#include <cuda_fp16.h>
#include <cstdint>

#define SEQ       128
#define BATCH     64
#define EMBED     512
#define HDIM      1024
#define NG        4096
#define TSTEPS    127
#define SEL_START 65
#define SEL_COUNT 62
#define MPAD      8192
#define NCTA      128

// ---------------- device scratch ----------------
__device__ __half g_Xh[MPAD * EMBED];          // fp16 embeddings (t-major)
__device__ __half g_Wih[NG * EMBED];           // fp16 w_ih, gate-interleaved rows
__device__ __half g_Whh[NG * HDIM];            // fp16 w_hh, gate-interleaved rows
__device__ float g_bsum[NG];
__device__ float g_P[TSTEPS * BATCH * NG];     // preacts, gate-interleaved cols
__device__ __half g_h2[2 * BATCH * HDIM];      // ping-pong h (fp16)
__device__ unsigned g_cnt[8][32];              // [quarter*2+half], 128B-spaced
__device__ int g_is64;

// ---------------- smem layout for lstm_persist (bytes) ----------------
#define OFF_H    0        // [32][1032] fp16 = 66048 (also W staging pre-loop)
#define OFF_PART 66048    // [4][32][68] f32 = 34816
#define OFF_PS   100864   // 2 x [32][64] f32 = 16384
#define SMEM_PERSIST 117248

// ---------------- gemm_pre smem: 3 stages x (A[128][72] + B[128][72]) fp16
#define GP_STAGE 36864
#define GP_SMEM  110592

// ---------------- helpers ----------------
__device__ __forceinline__ void mma16816h(float* c, const uint32_t* a, const uint32_t* b) {
    asm volatile(
        "mma.sync.aligned.m16n8k16.row.col.f32.f16.f16.f32 "
        "{%0,%1,%2,%3}, {%4,%5,%6,%7}, {%8,%9}, {%0,%1,%2,%3};\n"
        : "+f"(c[0]), "+f"(c[1]), "+f"(c[2]), "+f"(c[3])
        : "r"(a[0]), "r"(a[1]), "r"(a[2]), "r"(a[3]), "r"(b[0]), "r"(b[1]));
}
__device__ __forceinline__ void ldsm4(uint32_t* r, uint32_t saddr) {
    asm volatile("ldmatrix.sync.aligned.m8n8.x4.shared.b16 {%0,%1,%2,%3}, [%4];"
        : "=r"(r[0]), "=r"(r[1]), "=r"(r[2]), "=r"(r[3]) : "r"(saddr));
}
__device__ __forceinline__ uint32_t sptr(const void* p) {
    return (uint32_t)__cvta_generic_to_shared(p);
}
__device__ __forceinline__ void cpa16(void* smem, const void* g) {
    uint32_t s = sptr(smem);
    asm volatile("cp.async.cg.shared.global [%0], [%1], 16;\n" :: "r"(s), "l"(g));
}
__device__ __forceinline__ void cpa_commit() { asm volatile("cp.async.commit_group;\n"); }
__device__ __forceinline__ void cpa_wait2()  { asm volatile("cp.async.wait_group 2;\n"); }
__device__ __forceinline__ void cpa_wait1()  { asm volatile("cp.async.wait_group 1;\n"); }
__device__ __forceinline__ void cpa_wait0()  { asm volatile("cp.async.wait_group 0;\n"); }
__device__ __forceinline__ unsigned ldv(const unsigned* p) { return *(volatile const unsigned*)p; }
__device__ __forceinline__ float ex2f(float x) {
    float y; asm("ex2.approx.f32 %0, %1;" : "=f"(y) : "f"(x)); return y;
}
__device__ __forceinline__ float rcpf(float x) {
    float y; asm("rcp.approx.f32 %0, %1;" : "=f"(y) : "f"(x)); return y;
}
#define L2E  1.4426950408889634f
#define L2E2 2.8853900817779268f

// ---------------- fused init (detect + h0 + out + counters) ----------------
__global__ void fused_init(const int* __restrict__ prob32, const float* __restrict__ h0,
                           float* __restrict__ out, const float* __restrict__ b_ans) {
    int bid = blockIdx.x;
    if (bid == 0) {
        __shared__ int any;
        if (threadIdx.x == 0) any = 0;
        __syncthreads();
        int local = 0;
        for (int i = 2 * threadIdx.x + 1; i < BATCH * SEQ; i += 2 * blockDim.x)
            local |= prob32[i];
        if (local) atomicOr(&any, 1);
        __syncthreads();
        if (threadIdx.x == 0) g_is64 = (any == 0) ? 1 : 0;
        if (threadIdx.x < 8) g_cnt[threadIdx.x][0] = 0u;
    } else if (bid <= 64) {
        int i = (bid - 1) * 1024 + threadIdx.x;
        g_h2[i] = __float2half_rn(h0[i]);
    } else {
        int i = (bid - 65) * 1024 + threadIdx.x;
        if (i < BATCH * SEL_COUNT) out[i] = b_ans[0];
    }
}

// ---------------- merged prep: gather + weight conversion ----------------
__global__ void prep_all(const void* __restrict__ prob, const float* __restrict__ table,
                         const float* __restrict__ w_ih, const float* __restrict__ w_hh,
                         const float* __restrict__ b_ih, const float* __restrict__ b_hh) {
    int bid = blockIdx.x;
    int tid = threadIdx.x;
    if (bid < NG) {                       // w_ih -> fp16 (gate-interleaved)
        int n = bid;
        int j = n >> 2, g = n & 3;
        int r = g * HDIM + j;
        if (tid < 128) {
            float4 v = ((const float4*)(w_ih + (size_t)r * EMBED))[tid];
            int o = n * EMBED + tid * 4;
            g_Wih[o + 0] = __float2half_rn(v.x);
            g_Wih[o + 1] = __float2half_rn(v.y);
            g_Wih[o + 2] = __float2half_rn(v.z);
            g_Wih[o + 3] = __float2half_rn(v.w);
        }
        if (tid == 0) g_bsum[n] = b_ih[r] + b_hh[r];
    } else if (bid < 2 * NG) {            // w_hh -> fp16 (gate-interleaved)
        int n = bid - NG;
        int j = n >> 2, g = n & 3;
        int r = g * HDIM + j;
        float4 v = ((const float4*)(w_hh + (size_t)r * HDIM))[tid];
        int o = n * HDIM + tid * 4;
        g_Whh[o + 0] = __float2half_rn(v.x);
        g_Whh[o + 1] = __float2half_rn(v.y);
        g_Whh[o + 2] = __float2half_rn(v.z);
        g_Whh[o + 3] = __float2half_rn(v.w);
    } else {                              // gather: 2 rows per block
        int row = (bid - 2 * NG) * 2 + (tid >> 7);
        if (row < TSTEPS * BATCH) {
            int t = row >> 6, b = row & 63;
            long long tok;
            if (g_is64) tok = ((const long long*)prob)[b * SEQ + t];
            else        tok = (long long)((const int*)prob)[b * SEQ + t];
            int lt = tid & 127;
            float4 v = ((const float4*)(table + (size_t)tok * EMBED))[lt];
            int o = row * EMBED + lt * 4;
            g_Xh[o + 0] = __float2half_rn(v.x);
            g_Xh[o + 1] = __float2half_rn(v.y);
            g_Xh[o + 2] = __float2half_rn(v.z);
            g_Xh[o + 3] = __float2half_rn(v.w);
        }
    }
}

// ---------------- pre-GEMM: P = Xh @ Wih^T + bsum  [8192x4096, K=512] -----
__global__ __launch_bounds__(256, 2)
void gemm_pre() {
    extern __shared__ char gsm[];
    const int tid = threadIdx.x, warp = tid >> 5, lane = tid & 31;
    const int gid = lane >> 2, kb = (lane & 3) << 1;
    const int m_off = (warp >> 2) << 6;   // 0,64
    const int n_off = (warp & 3) << 5;    // 0,32,64,96
    const int m0 = blockIdx.y << 7;
    const int n0 = blockIdx.x << 7;
    const int a_r = (lane & 7) + (lane & 8);
    const int a_c = (lane & 16) >> 1;
    const int b_r = (lane & 7) + ((lane & 16) >> 1);
    const int b_c = (lane & 8);

    float acc[4][4][4];
#pragma unroll
    for (int a = 0; a < 4; a++)
#pragma unroll
        for (int b = 0; b < 4; b++)
#pragma unroll
            for (int cc = 0; cc < 4; cc++) acc[a][b][cc] = 0.0f;

    auto load_stage = [&](int s, int k0) {
        char* base = gsm + s * GP_STAGE;
#pragma unroll
        for (int it = 0; it < 8; it++) {
            int op = it * 256 + tid;
            int r = (op & 1023) >> 3;
            int c = op & 7;
            if (op < 1024)
                cpa16(base + r * 144 + c * 16,
                      g_Xh + (size_t)(m0 + r) * EMBED + k0 + c * 8);
            else
                cpa16(base + 18432 + r * 144 + c * 16,
                      g_Wih + (size_t)(n0 + r) * EMBED + k0 + c * 8);
        }
        cpa_commit();
    };

    auto compute = [&](int s) {
        uint32_t sA = sptr(gsm + s * GP_STAGE);
        uint32_t sAo = sA + (uint32_t)((m_off + a_r) * 72 + a_c) * 2;
        uint32_t sBo = sA + 18432 + (uint32_t)((n_off + b_r) * 72 + b_c) * 2;
#pragma unroll
        for (int ks = 0; ks < 64; ks += 16) {
            uint32_t ah[4][4], bh4[2][4];
#pragma unroll
            for (int mf = 0; mf < 4; mf++)
                ldsm4(ah[mf], sAo + (uint32_t)(mf * 16 * 72 + ks) * 2);
#pragma unroll
            for (int nh = 0; nh < 2; nh++)
                ldsm4(bh4[nh], sBo + (uint32_t)(nh * 16 * 72 + ks) * 2);
#pragma unroll
            for (int nf = 0; nf < 4; nf++) {
                const uint32_t* bh = &bh4[nf >> 1][(nf & 1) * 2];
#pragma unroll
                for (int mf = 0; mf < 4; mf++)
                    mma16816h(acc[mf][nf], ah[mf], bh);
            }
        }
    };

    const int KT = EMBED / 64;   // 8
    load_stage(0, 0);
    load_stage(1, 64);
    for (int kt = 0; kt < KT; kt++) {
        if (kt < KT - 1) cpa_wait1(); else cpa_wait0();
        __syncthreads();
        if (kt + 2 < KT) load_stage((kt + 2) % 3, (kt + 2) * 64);
        compute(kt % 3);
    }

#pragma unroll
    for (int mf = 0; mf < 4; mf++)
#pragma unroll
        for (int nf = 0; nf < 4; nf++) {
            int row = m0 + m_off + mf * 16 + gid;
            int col = n0 + n_off + nf * 8 + kb;
            float b0 = g_bsum[col], b1 = g_bsum[col + 1];
            if (row < TSTEPS * BATCH) {
                g_P[(size_t)row * NG + col]     = acc[mf][nf][0] + b0;
                g_P[(size_t)row * NG + col + 1] = acc[mf][nf][1] + b1;
            }
            if (row + 8 < TSTEPS * BATCH) {
                g_P[(size_t)(row + 8) * NG + col]     = acc[mf][nf][2] + b0;
                g_P[(size_t)(row + 8) * NG + col + 1] = acc[mf][nf][3] + b1;
            }
        }
}

// ---------------- persistent recurrent kernel -----------------------------
// 128 CTAs = 64 col-groups x 2 batch-halves; 8 warps = 4 K-quarters x 2
// N-halves; weights register-resident; h load 2-chunk pipelined vs MMA;
// atomic-counter sync (R13 semantics) with release-RED publish.
__global__ __launch_bounds__(256, 1)
void lstm_persist(const float* __restrict__ c0, const float* __restrict__ w_ans,
                  float* __restrict__ out) {
    extern __shared__ char smc[];
    const int tid = threadIdx.x, warp = tid >> 5, lane = tid & 31;
    const int gid = lane >> 2, kb = (lane & 3) << 1;
    const int kq = warp >> 1;             // 0..3 K quarter
    const int nh = warp & 1;              // 0..1 N half (32 cols)
    const int cg = blockIdx.x >> 1;       // column group 0..63
    const int bh = blockIdx.x & 1;        // batch half
    const int n0 = cg << 6;               // 64 gate cols
    const int j0 = cg << 4;               // 16 j's
    const int b0 = bh << 5;               // 32 batch rows
    const int a_r = (lane & 7) + (lane & 8);
    const int a_c = (lane & 16) >> 1;
    const int b_r = (lane & 7) + ((lane & 16) >> 1);
    const int b_c = (lane & 8);
    const int grp_c = kq * 2 + bh;            // counter this warp consumes
    const int grp_p = (cg >> 4) * 2 + bh;     // counter this CTA produces

    float* part = (float*)(smc + OFF_PART);   // [4][32][68]

    // ---- stage W (64 cols x 1024) through h region in two 32-col passes ----
    uint32_t Breg[16][8];
#pragma unroll
    for (int st = 0; st < 2; st++) {
#pragma unroll
        for (int it = 0; it < 16; it++) {
            int op = it * 256 + tid;          // 0..4095
            int r = op >> 7, c = op & 127;
            cpa16(smc + OFF_H + (size_t)r * 2064 + c * 16,
                  g_Whh + (size_t)(n0 + st * 32 + r) * HDIM + c * 8);
        }
        cpa_commit(); cpa_wait0();
        __syncthreads();
        if (nh == st) {
            uint32_t sW = sptr(smc + OFF_H) + (uint32_t)(b_r * 2064) + (uint32_t)b_c * 2;
#pragma unroll
            for (int kf = 0; kf < 16; kf++) {
                uint32_t koff = (uint32_t)(kq * 256 + kf * 16) * 2;
                ldsm4(&Breg[kf][0], sW + koff);
                ldsm4(&Breg[kf][4], sW + 16u * 2064 + koff);
            }
        }
        __syncthreads();
    }

    // ---- per-thread state in registers: c and w_ans for (b, jj) items ----
    float c_reg[2], was_reg[2];
#pragma unroll
    for (int half = 0; half < 2; half++) {
        int idx = tid + half * 256;
        int b = idx >> 4, jj = idx & 15;
        c_reg[half]   = c0[(size_t)(b0 + b) * HDIM + j0 + jj];
        was_reg[half] = w_ans[j0 + jj];
    }

    const uint32_t sAB = sptr(smc + OFF_H) + (uint32_t)(a_r * 2064) + (uint32_t)a_c * 2;

    // P(0) prologue load into Ps buf 0
    {
#pragma unroll
        for (int it = 0; it < 2; it++) {
            int op = it * 256 + tid;          // 0..511
            int r = op >> 4, c = op & 15;
            cpa16(smc + OFF_PS + r * 256 + c * 16,
                  g_P + (size_t)(b0 + r) * NG + n0 + c * 4);
        }
        cpa_commit();
    }

    for (int t = 0; t < TSTEPS; t++) {
        const __half* hsrc = g_h2 + (size_t)(t & 1) * (BATCH * HDIM);
        __half* hdst = g_h2 + (size_t)((t + 1) & 1) * (BATCH * HDIM);

        // ---- fine-grained wait: this warp's h quarter ready ----
        if (lane == 0) {
            unsigned tgt = 16u * (unsigned)t;
            while (ldv(&g_cnt[grp_c][0]) < tgt) { }
            __threadfence();
        }
        __syncwarp();

        // ---- h quarter in 2 K-chunks (16 rows x 128 cols each per warp) ----
#pragma unroll
        for (int ck = 0; ck < 2; ck++) {
#pragma unroll
            for (int it = 0; it < 8; it++) {
                int idx = it * 32 + lane;         // 0..255
                int r = nh * 16 + (idx >> 4), ch = (idx & 15) + ck * 16;
                cpa16(smc + OFF_H + (size_t)r * 2064 + (size_t)(kq * 512 + ch * 16),
                      hsrc + (size_t)(b0 + r) * HDIM + kq * 256 + ch * 8);
            }
            cpa_commit();
        }
        // ---- prefetch P(t+1) last (consumed next step; stays in flight) ----
        {
            int tp = (t + 1 < TSTEPS) ? (t + 1) : 0;
#pragma unroll
            for (int it = 0; it < 2; it++) {
                int op = it * 256 + tid;
                int r = op >> 4, c = op & 15;
                cpa16(smc + OFF_PS + ((t + 1) & 1) * 8192 + r * 256 + c * 16,
                      g_P + ((size_t)tp * BATCH + b0 + r) * NG + n0 + c * 4);
            }
            cpa_commit();
        }

        float acc[2][4][4];
#pragma unroll
        for (int a = 0; a < 2; a++)
#pragma unroll
            for (int b = 0; b < 4; b++)
#pragma unroll
                for (int q = 0; q < 4; q++) acc[a][b][q] = 0.0f;

        // ---- chunk0 ready (also drains P(t) from last step) -> MMA kf 0..7
        cpa_wait2();
        asm volatile("bar.sync %0, 64;" :: "r"(1 + kq) : "memory");
#pragma unroll
        for (int kf = 0; kf < 8; kf++) {
            uint32_t koff = (uint32_t)(kq * 256 + kf * 16) * 2;
            uint32_t ah[2][4];
            ldsm4(ah[0], sAB + koff);
            ldsm4(ah[1], sAB + 16u * 2064 + koff);
#pragma unroll
            for (int mf = 0; mf < 2; mf++)
#pragma unroll
                for (int nf = 0; nf < 4; nf++)
                    mma16816h(acc[mf][nf], ah[mf], &Breg[kf][nf * 2]);
        }
        // ---- chunk1 ready -> MMA kf 8..15 (P(t+1) still in flight) ----
        cpa_wait1();
        asm volatile("bar.sync %0, 64;" :: "r"(1 + kq) : "memory");
#pragma unroll
        for (int kf = 8; kf < 16; kf++) {
            uint32_t koff = (uint32_t)(kq * 256 + kf * 16) * 2;
            uint32_t ah[2][4];
            ldsm4(ah[0], sAB + koff);
            ldsm4(ah[1], sAB + 16u * 2064 + koff);
#pragma unroll
            for (int mf = 0; mf < 2; mf++)
#pragma unroll
                for (int nf = 0; nf < 4; nf++)
                    mma16816h(acc[mf][nf], ah[mf], &Breg[kf][nf * 2]);
        }

        // ---- store K-partials: part[kq][row 0..31][col 0..63] ----
        {
            float* pk = part + kq * 2176;     // 32*68
#pragma unroll
            for (int mf = 0; mf < 2; mf++)
#pragma unroll
                for (int nf = 0; nf < 4; nf++) {
                    int col = nh * 32 + nf * 8 + kb;
                    int row = mf * 16 + gid;
                    *(float2*)(pk + row * 68 + col)       = make_float2(acc[mf][nf][0], acc[mf][nf][1]);
                    *(float2*)(pk + (row + 8) * 68 + col) = make_float2(acc[mf][nf][2], acc[mf][nf][3]);
                }
        }
        __syncthreads();

        // ---- reduce partials + cell; store h; stash answer-dot term ----
        const float* Ps = (const float*)(smc + OFF_PS + (t & 1) * 8192);
        float pstash[2];
#pragma unroll
        for (int half = 0; half < 2; half++) {
            int idx = tid + half * 256;
            int b = idx >> 4, jj = idx & 15;
            const float* pb = part + b * 68 + jj * 4;
            float4 s0 = *(const float4*)(pb);
            float4 s1 = *(const float4*)(pb + 2176);
            float4 s2 = *(const float4*)(pb + 4352);
            float4 s3 = *(const float4*)(pb + 6528);
            float4 pv = *(const float4*)(Ps + b * 64 + jj * 4);
            float gi = s0.x + s1.x + s2.x + s3.x + pv.x;
            float gf = s0.y + s1.y + s2.y + s3.y + pv.y;
            float gg = s0.z + s1.z + s2.z + s3.z + pv.z;
            float go = s0.w + s1.w + s2.w + s3.w + pv.w;
            gi = fminf(fmaxf(gi, -15.0f), 15.0f);
            gf = fminf(fmaxf(gf, -15.0f), 15.0f);
            gg = fminf(fmaxf(gg, -15.0f), 15.0f);
            go = fminf(fmaxf(go, -15.0f), 15.0f);
            float ei = ex2f(-gi * L2E);
            float ef = ex2f(-gf * L2E);
            float eo = ex2f(-go * L2E);
            float d1 = 1.0f + ei, d2 = 1.0f + ef, d3 = 1.0f + eo;
            float m12 = d1 * d2, m23 = d2 * d3, m13 = d1 * d3;
            float r = rcpf(m12 * d3);
            float si = r * m23, sf = r * m13, so = r * m12;
            float eg = ex2f(gg * L2E2);
            float tg = (eg - 1.0f) * rcpf(eg + 1.0f);
            float c = sf * c_reg[half] + si * tg;
            c_reg[half] = c;
            float ac = fminf(fmaxf(c * L2E2, -60.0f), 60.0f);
            float ec = ex2f(ac);
            float tc = (ec - 1.0f) * rcpf(ec + 1.0f);
            float h = so * tc;
            hdst[(size_t)(b0 + b) * HDIM + j0 + jj] = __float2half_rn(h);
            pstash[half] = h * was_reg[half];
        }

        // ---- publish h(t+1): barrier happens-before + release RED ----
        __syncthreads();
        if (tid == 0)
            asm volatile("red.release.gpu.global.add.u32 [%0], %1;"
                         :: "l"(&g_cnt[grp_p][0]), "r"(1u) : "memory");

        if (t >= SEL_START) {
#pragma unroll
            for (int half = 0; half < 2; half++) {
                int idx = tid + half * 256;
                int b = idx >> 4;
                float p = pstash[half];
                p += __shfl_xor_sync(0xFFFFFFFFu, p, 8);
                p += __shfl_xor_sync(0xFFFFFFFFu, p, 4);
                p += __shfl_xor_sync(0xFFFFFFFFu, p, 2);
                p += __shfl_xor_sync(0xFFFFFFFFu, p, 1);
                if ((lane & 15) == 0)
                    atomicAdd(&out[(b0 + b) * SEL_COUNT + (t - SEL_START)], p);
            }
        }
    }
}

// ---------------- launch ----------------
extern "C" void kernel_launch(void* const* d_in, const int* in_sizes, int n_in,
                              void* d_out, int out_size) {
    (void)in_sizes; (void)n_in; (void)out_size;
    const void*  prob  = d_in[0];
    const float* table = (const float*)d_in[2];
    const float* w_ih  = (const float*)d_in[3];
    const float* w_hh  = (const float*)d_in[4];
    const float* b_ih  = (const float*)d_in[5];
    const float* b_hh  = (const float*)d_in[6];
    const float* w_ans = (const float*)d_in[7];
    const float* b_ans = (const float*)d_in[8];
    const float* h0    = (const float*)d_in[9];
    const float* c0    = (const float*)d_in[10];
    float* out = (float*)d_out;

    static bool inited = false;
    if (!inited) {
        cudaFuncSetAttribute(gemm_pre,     cudaFuncAttributeMaxDynamicSharedMemorySize, GP_SMEM);
        cudaFuncSetAttribute(lstm_persist, cudaFuncAttributeMaxDynamicSharedMemorySize, SMEM_PERSIST);
        inited = true;
    }

    fused_init<<<69, 1024>>>((const int*)prob, h0, out, b_ans);
    prep_all<<<2 * NG + (TSTEPS * BATCH + 1) / 2, 256>>>(prob, table, w_ih, w_hh, b_ih, b_hh);
    gemm_pre<<<dim3(NG / 128, MPAD / 128), 256, GP_SMEM>>>();
    lstm_persist<<<NCTA, 256, SMEM_PERSIST>>>(c0, w_ans, out);
}

// round 16
// speedup vs baseline: 2.4911x; 1.0816x over previous
#include <cuda_runtime.h>
#include <cuda_bf16.h>
#include <cuda_fp16.h>
#include <cstdint>

#define SEQ       128
#define BATCH     64
#define EMBED     512
#define HDIM      1024
#define NG        4096
#define TSTEPS    127
#define SEL_START 65
#define SEL_COUNT 62
#define MPAD      8192
#define NCTA      128

// ---------------- device scratch ----------------
__device__ __half g_Xh[MPAD * EMBED];          // fp16 embeddings (t-major)
__device__ __half g_Wih[NG * EMBED];           // fp16 w_ih, gate-interleaved rows
__device__ __half g_Whh[NG * HDIM];            // fp16 w_hh, gate-interleaved rows
__device__ float g_bsum[NG];
__device__ float g_P[TSTEPS * BATCH * NG];     // preacts, gate-interleaved cols
__device__ __half g_h2[2 * BATCH * HDIM];      // ping-pong h (fp16)
__device__ unsigned g_cnt[8][32];              // [quarter*2+half], 128B-spaced
__device__ int g_is64;

// ---------------- smem layout for lstm_persist (bytes) ----------------
#define OFF_H    0        // [32][1032] fp16 = 66048 (also W staging pre-loop)
#define OFF_PART 66048    // [4][32][68] f32 = 34816
#define OFF_PS   100864   // 2 x [32][64] f32 = 16384
#define SMEM_PERSIST 117248

// ---------------- gemm_pre smem: 3 stages x (A[128][72] + B[128][72]) fp16
#define GP_STAGE 36864
#define GP_SMEM  110592

// ---------------- helpers ----------------
__device__ __forceinline__ void mma16816h(float* c, const uint32_t* a, const uint32_t* b) {
    asm volatile(
        "mma.sync.aligned.m16n8k16.row.col.f32.f16.f16.f32 "
        "{%0,%1,%2,%3}, {%4,%5,%6,%7}, {%8,%9}, {%0,%1,%2,%3};\n"
        : "+f"(c[0]), "+f"(c[1]), "+f"(c[2]), "+f"(c[3])
        : "r"(a[0]), "r"(a[1]), "r"(a[2]), "r"(a[3]), "r"(b[0]), "r"(b[1]));
}
__device__ __forceinline__ void ldsm4(uint32_t* r, uint32_t saddr) {
    asm volatile("ldmatrix.sync.aligned.m8n8.x4.shared.b16 {%0,%1,%2,%3}, [%4];"
        : "=r"(r[0]), "=r"(r[1]), "=r"(r[2]), "=r"(r[3]) : "r"(saddr));
}
__device__ __forceinline__ uint32_t sptr(const void* p) {
    return (uint32_t)__cvta_generic_to_shared(p);
}
__device__ __forceinline__ void cpa16(void* smem, const void* g) {
    uint32_t s = sptr(smem);
    asm volatile("cp.async.cg.shared.global [%0], [%1], 16;\n" :: "r"(s), "l"(g));
}
__device__ __forceinline__ void cpa_commit() { asm volatile("cp.async.commit_group;\n"); }
__device__ __forceinline__ void cpa_wait2()  { asm volatile("cp.async.wait_group 2;\n"); }
__device__ __forceinline__ void cpa_wait1()  { asm volatile("cp.async.wait_group 1;\n"); }
__device__ __forceinline__ void cpa_wait0()  { asm volatile("cp.async.wait_group 0;\n"); }
__device__ __forceinline__ unsigned ldacq(const unsigned* p) {
    unsigned v;
    asm volatile("ld.acquire.gpu.global.u32 %0, [%1];" : "=r"(v) : "l"(p) : "memory");
    return v;
}
__device__ __forceinline__ float ex2f(float x) {
    float y; asm("ex2.approx.f32 %0, %1;" : "=f"(y) : "f"(x)); return y;
}
__device__ __forceinline__ uint32_t ex2h2(uint32_t x) {
    uint32_t y; asm("ex2.approx.f16x2 %0, %1;" : "=r"(y) : "r"(x)); return y;
}
__device__ __forceinline__ float rcpf(float x) {
    float y; asm("rcp.approx.f32 %0, %1;" : "=f"(y) : "f"(x)); return y;
}
#define L2E  1.4426950408889634f
#define L2E2 2.8853900817779268f

// ---------------- fused init (detect + h0 + out + counters) ----------------
__global__ void fused_init(const int* __restrict__ prob32, const float* __restrict__ h0,
                           float* __restrict__ out, const float* __restrict__ b_ans) {
    int bid = blockIdx.x;
    if (bid == 0) {
        __shared__ int any;
        if (threadIdx.x == 0) any = 0;
        __syncthreads();
        int local = 0;
        for (int i = 2 * threadIdx.x + 1; i < BATCH * SEQ; i += 2 * blockDim.x)
            local |= prob32[i];
        if (local) atomicOr(&any, 1);
        __syncthreads();
        if (threadIdx.x == 0) g_is64 = (any == 0) ? 1 : 0;
        if (threadIdx.x < 8) g_cnt[threadIdx.x][0] = 0u;
    } else if (bid <= 64) {
        int i = (bid - 1) * 1024 + threadIdx.x;
        g_h2[i] = __float2half_rn(h0[i]);
    } else {
        int i = (bid - 65) * 1024 + threadIdx.x;
        if (i < BATCH * SEL_COUNT) out[i] = b_ans[0];
    }
}

// ---------------- merged prep: gather + weight conversion ----------------
__global__ void prep_all(const void* __restrict__ prob, const float* __restrict__ table,
                         const float* __restrict__ w_ih, const float* __restrict__ w_hh,
                         const float* __restrict__ b_ih, const float* __restrict__ b_hh) {
    int bid = blockIdx.x;
    int tid = threadIdx.x;
    if (bid < NG) {                       // w_ih -> fp16 (gate-interleaved)
        int n = bid;
        int j = n >> 2, g = n & 3;
        int r = g * HDIM + j;
        if (tid < 128) {
            float4 v = ((const float4*)(w_ih + (size_t)r * EMBED))[tid];
            int o = n * EMBED + tid * 4;
            g_Wih[o + 0] = __float2half_rn(v.x);
            g_Wih[o + 1] = __float2half_rn(v.y);
            g_Wih[o + 2] = __float2half_rn(v.z);
            g_Wih[o + 3] = __float2half_rn(v.w);
        }
        if (tid == 0) g_bsum[n] = b_ih[r] + b_hh[r];
    } else if (bid < 2 * NG) {            // w_hh -> fp16 (gate-interleaved)
        int n = bid - NG;
        int j = n >> 2, g = n & 3;
        int r = g * HDIM + j;
        float4 v = ((const float4*)(w_hh + (size_t)r * HDIM))[tid];
        int o = n * HDIM + tid * 4;
        g_Whh[o + 0] = __float2half_rn(v.x);
        g_Whh[o + 1] = __float2half_rn(v.y);
        g_Whh[o + 2] = __float2half_rn(v.z);
        g_Whh[o + 3] = __float2half_rn(v.w);
    } else {                              // gather: 2 rows per block
        int row = (bid - 2 * NG) * 2 + (tid >> 7);
        if (row < TSTEPS * BATCH) {
            int t = row >> 6, b = row & 63;
            long long tok;
            if (g_is64) tok = ((const long long*)prob)[b * SEQ + t];
            else        tok = (long long)((const int*)prob)[b * SEQ + t];
            int lt = tid & 127;
            float4 v = ((const float4*)(table + (size_t)tok * EMBED))[lt];
            int o = row * EMBED + lt * 4;
            g_Xh[o + 0] = __float2half_rn(v.x);
            g_Xh[o + 1] = __float2half_rn(v.y);
            g_Xh[o + 2] = __float2half_rn(v.z);
            g_Xh[o + 3] = __float2half_rn(v.w);
        }
    }
}

// ---------------- pre-GEMM: P = Xh @ Wih^T + bsum  [8192x4096, K=512] -----
__global__ __launch_bounds__(256, 2)
void gemm_pre() {
    extern __shared__ char gsm[];
    const int tid = threadIdx.x, warp = tid >> 5, lane = tid & 31;
    const int gid = lane >> 2, kb = (lane & 3) << 1;
    const int m_off = (warp >> 2) << 6;   // 0,64
    const int n_off = (warp & 3) << 5;    // 0,32,64,96
    const int m0 = blockIdx.y << 7;
    const int n0 = blockIdx.x << 7;
    const int a_r = (lane & 7) + (lane & 8);
    const int a_c = (lane & 16) >> 1;
    const int b_r = (lane & 7) + ((lane & 16) >> 1);
    const int b_c = (lane & 8);

    float acc[4][4][4];
#pragma unroll
    for (int a = 0; a < 4; a++)
#pragma unroll
        for (int b = 0; b < 4; b++)
#pragma unroll
            for (int cc = 0; cc < 4; cc++) acc[a][b][cc] = 0.0f;

    auto load_stage = [&](int s, int k0) {
        char* base = gsm + s * GP_STAGE;
#pragma unroll
        for (int it = 0; it < 8; it++) {
            int op = it * 256 + tid;
            int r = (op & 1023) >> 3;
            int c = op & 7;
            if (op < 1024)
                cpa16(base + r * 144 + c * 16,
                      g_Xh + (size_t)(m0 + r) * EMBED + k0 + c * 8);
            else
                cpa16(base + 18432 + r * 144 + c * 16,
                      g_Wih + (size_t)(n0 + r) * EMBED + k0 + c * 8);
        }
        cpa_commit();
    };

    auto compute = [&](int s) {
        uint32_t sA = sptr(gsm + s * GP_STAGE);
        uint32_t sAo = sA + (uint32_t)((m_off + a_r) * 72 + a_c) * 2;
        uint32_t sBo = sA + 18432 + (uint32_t)((n_off + b_r) * 72 + b_c) * 2;
#pragma unroll
        for (int ks = 0; ks < 64; ks += 16) {
            uint32_t ah[4][4], bh4[2][4];
#pragma unroll
            for (int mf = 0; mf < 4; mf++)
                ldsm4(ah[mf], sAo + (uint32_t)(mf * 16 * 72 + ks) * 2);
#pragma unroll
            for (int nh = 0; nh < 2; nh++)
                ldsm4(bh4[nh], sBo + (uint32_t)(nh * 16 * 72 + ks) * 2);
#pragma unroll
            for (int nf = 0; nf < 4; nf++) {
                const uint32_t* bh = &bh4[nf >> 1][(nf & 1) * 2];
#pragma unroll
                for (int mf = 0; mf < 4; mf++)
                    mma16816h(acc[mf][nf], ah[mf], bh);
            }
        }
    };

    const int KT = EMBED / 64;   // 8
    load_stage(0, 0);
    load_stage(1, 64);
    for (int kt = 0; kt < KT; kt++) {
        if (kt < KT - 1) cpa_wait1(); else cpa_wait0();
        __syncthreads();
        if (kt + 2 < KT) load_stage((kt + 2) % 3, (kt + 2) * 64);
        compute(kt % 3);
    }

#pragma unroll
    for (int mf = 0; mf < 4; mf++)
#pragma unroll
        for (int nf = 0; nf < 4; nf++) {
            int row = m0 + m_off + mf * 16 + gid;
            int col = n0 + n_off + nf * 8 + kb;
            float b0 = g_bsum[col], b1 = g_bsum[col + 1];
            if (row < TSTEPS * BATCH) {
                g_P[(size_t)row * NG + col]     = acc[mf][nf][0] + b0;
                g_P[(size_t)row * NG + col + 1] = acc[mf][nf][1] + b1;
            }
            if (row + 8 < TSTEPS * BATCH) {
                g_P[(size_t)(row + 8) * NG + col]     = acc[mf][nf][2] + b0;
                g_P[(size_t)(row + 8) * NG + col + 1] = acc[mf][nf][3] + b1;
            }
        }
}

// ---------------- persistent recurrent kernel -----------------------------
// 128 CTAs = 64 col-groups x 2 batch-halves; 8 warps = 4 K-quarters x 2
// N-halves; weights register-resident; h load 2-chunk pipelined vs MMA;
// atomic-counter sync with release-RED publish; MUFU-reduced cell.
__global__ __launch_bounds__(256, 1)
void lstm_persist(const float* __restrict__ c0, const float* __restrict__ w_ans,
                  float* __restrict__ out) {
    extern __shared__ char smc[];
    const int tid = threadIdx.x, warp = tid >> 5, lane = tid & 31;
    const int gid = lane >> 2, kb = (lane & 3) << 1;
    const int kq = warp >> 1;             // 0..3 K quarter
    const int nh = warp & 1;              // 0..1 N half (32 cols)
    const int cg = blockIdx.x >> 1;       // column group 0..63
    const int bh = blockIdx.x & 1;        // batch half
    const int n0 = cg << 6;               // 64 gate cols
    const int j0 = cg << 4;               // 16 j's
    const int b0 = bh << 5;               // 32 batch rows
    const int a_r = (lane & 7) + (lane & 8);
    const int a_c = (lane & 16) >> 1;
    const int b_r = (lane & 7) + ((lane & 16) >> 1);
    const int b_c = (lane & 8);
    const int grp_c = kq * 2 + bh;            // counter this warp consumes
    const int grp_p = (cg >> 4) * 2 + bh;     // counter this CTA produces

    float* part = (float*)(smc + OFF_PART);   // [4][32][68]

    // ---- stage W (64 cols x 1024) through h region in two 32-col passes ----
    uint32_t Breg[16][8];
#pragma unroll
    for (int st = 0; st < 2; st++) {
#pragma unroll
        for (int it = 0; it < 16; it++) {
            int op = it * 256 + tid;          // 0..4095
            int r = op >> 7, c = op & 127;
            cpa16(smc + OFF_H + (size_t)r * 2064 + c * 16,
                  g_Whh + (size_t)(n0 + st * 32 + r) * HDIM + c * 8);
        }
        cpa_commit(); cpa_wait0();
        __syncthreads();
        if (nh == st) {
            uint32_t sW = sptr(smc + OFF_H) + (uint32_t)(b_r * 2064) + (uint32_t)b_c * 2;
#pragma unroll
            for (int kf = 0; kf < 16; kf++) {
                uint32_t koff = (uint32_t)(kq * 256 + kf * 16) * 2;
                ldsm4(&Breg[kf][0], sW + koff);
                ldsm4(&Breg[kf][4], sW + 16u * 2064 + koff);
            }
        }
        __syncthreads();
    }

    // ---- per-thread state in registers: c and w_ans for (b, jj) items ----
    float c_reg[2], was_reg[2];
#pragma unroll
    for (int half = 0; half < 2; half++) {
        int idx = tid + half * 256;
        int b = idx >> 4, jj = idx & 15;
        c_reg[half]   = c0[(size_t)(b0 + b) * HDIM + j0 + jj];
        was_reg[half] = w_ans[j0 + jj];
    }

    const uint32_t sAB = sptr(smc + OFF_H) + (uint32_t)(a_r * 2064) + (uint32_t)a_c * 2;

    // P(0) prologue load into Ps buf 0
    {
#pragma unroll
        for (int it = 0; it < 2; it++) {
            int op = it * 256 + tid;          // 0..511
            int r = op >> 4, c = op & 15;
            cpa16(smc + OFF_PS + r * 256 + c * 16,
                  g_P + (size_t)(b0 + r) * NG + n0 + c * 4);
        }
        cpa_commit();
    }

    for (int t = 0; t < TSTEPS; t++) {
        const __half* hsrc = g_h2 + (size_t)(t & 1) * (BATCH * HDIM);
        __half* hdst = g_h2 + (size_t)((t + 1) & 1) * (BATCH * HDIM);

        // ---- fine-grained wait (acquire): this warp's h quarter ready ----
        if (lane == 0) {
            unsigned tgt = 16u * (unsigned)t;
            while (ldacq(&g_cnt[grp_c][0]) < tgt) { }
        }
        __syncwarp();

        // ---- h quarter in 2 K-chunks (16 rows x 128 cols each per warp) ----
#pragma unroll
        for (int ck = 0; ck < 2; ck++) {
#pragma unroll
            for (int it = 0; it < 8; it++) {
                int idx = it * 32 + lane;         // 0..255
                int r = nh * 16 + (idx >> 4), ch = (idx & 15) + ck * 16;
                cpa16(smc + OFF_H + (size_t)r * 2064 + (size_t)(kq * 512 + ch * 16),
                      hsrc + (size_t)(b0 + r) * HDIM + kq * 256 + ch * 8);
            }
            cpa_commit();
        }
        // ---- prefetch P(t+1) last (consumed next step; stays in flight) ----
        {
            int tp = (t + 1 < TSTEPS) ? (t + 1) : 0;
#pragma unroll
            for (int it = 0; it < 2; it++) {
                int op = it * 256 + tid;
                int r = op >> 4, c = op & 15;
                cpa16(smc + OFF_PS + ((t + 1) & 1) * 8192 + r * 256 + c * 16,
                      g_P + ((size_t)tp * BATCH + b0 + r) * NG + n0 + c * 4);
            }
            cpa_commit();
        }

        float acc[2][4][4];
#pragma unroll
        for (int a = 0; a < 2; a++)
#pragma unroll
            for (int b = 0; b < 4; b++)
#pragma unroll
                for (int q = 0; q < 4; q++) acc[a][b][q] = 0.0f;

        // ---- chunk0 ready (also drains P(t) from last step) -> MMA kf 0..7
        cpa_wait2();
        asm volatile("bar.sync %0, 64;" :: "r"(1 + kq) : "memory");
#pragma unroll
        for (int kf = 0; kf < 8; kf++) {
            uint32_t koff = (uint32_t)(kq * 256 + kf * 16) * 2;
            uint32_t ah[2][4];
            ldsm4(ah[0], sAB + koff);
            ldsm4(ah[1], sAB + 16u * 2064 + koff);
#pragma unroll
            for (int mf = 0; mf < 2; mf++)
#pragma unroll
                for (int nf = 0; nf < 4; nf++)
                    mma16816h(acc[mf][nf], ah[mf], &Breg[kf][nf * 2]);
        }
        // ---- chunk1 ready -> MMA kf 8..15 (P(t+1) still in flight) ----
        cpa_wait1();
        asm volatile("bar.sync %0, 64;" :: "r"(1 + kq) : "memory");
#pragma unroll
        for (int kf = 8; kf < 16; kf++) {
            uint32_t koff = (uint32_t)(kq * 256 + kf * 16) * 2;
            uint32_t ah[2][4];
            ldsm4(ah[0], sAB + koff);
            ldsm4(ah[1], sAB + 16u * 2064 + koff);
#pragma unroll
            for (int mf = 0; mf < 2; mf++)
#pragma unroll
                for (int nf = 0; nf < 4; nf++)
                    mma16816h(acc[mf][nf], ah[mf], &Breg[kf][nf * 2]);
        }

        // ---- store K-partials: part[kq][row 0..31][col 0..63] ----
        {
            float* pk = part + kq * 2176;     // 32*68
#pragma unroll
            for (int mf = 0; mf < 2; mf++)
#pragma unroll
                for (int nf = 0; nf < 4; nf++) {
                    int col = nh * 32 + nf * 8 + kb;
                    int row = mf * 16 + gid;
                    *(float2*)(pk + row * 68 + col)       = make_float2(acc[mf][nf][0], acc[mf][nf][1]);
                    *(float2*)(pk + (row + 8) * 68 + col) = make_float2(acc[mf][nf][2], acc[mf][nf][3]);
                }
        }
        __syncthreads();

        // ---- reduce partials + MUFU-reduced cell; store h; stash dot term --
        const float* Ps = (const float*)(smc + OFF_PS + (t & 1) * 8192);
        float G[2][4];
#pragma unroll
        for (int half = 0; half < 2; half++) {
            int idx = tid + half * 256;
            int b = idx >> 4, jj = idx & 15;
            const float* pb = part + b * 68 + jj * 4;
            float4 s0 = *(const float4*)(pb);
            float4 s1 = *(const float4*)(pb + 2176);
            float4 s2 = *(const float4*)(pb + 4352);
            float4 s3 = *(const float4*)(pb + 6528);
            float4 pv = *(const float4*)(Ps + b * 64 + jj * 4);
            G[half][0] = fminf(fmaxf(s0.x + s1.x + s2.x + s3.x + pv.x, -11.0f), 11.0f);
            G[half][1] = fminf(fmaxf(s0.y + s1.y + s2.y + s3.y + pv.y, -11.0f), 11.0f);
            G[half][2] = fminf(fmaxf(s0.z + s1.z + s2.z + s3.z + pv.z, -15.0f), 15.0f);
            G[half][3] = fminf(fmaxf(s0.w + s1.w + s2.w + s3.w + pv.w, -11.0f), 11.0f);
        }
        // packed sigmoid exps: (ei,ef) per half + (eo0,eo1)
        __half2 pif0 = __floats2half2_rn(-G[0][0] * L2E, -G[0][1] * L2E);
        __half2 pif1 = __floats2half2_rn(-G[1][0] * L2E, -G[1][1] * L2E);
        __half2 poo  = __floats2half2_rn(-G[0][3] * L2E, -G[1][3] * L2E);
        __half2 eif0 = __halves2half2(__half(0), __half(0));
        *(uint32_t*)&eif0 = ex2h2(*(uint32_t*)&pif0);
        __half2 eif1; *(uint32_t*)&eif1 = ex2h2(*(uint32_t*)&pif1);
        __half2 eoo;  *(uint32_t*)&eoo  = ex2h2(*(uint32_t*)&poo);
        float eiA[2] = { __low2float(eif0),  __low2float(eif1) };
        float efA[2] = { __high2float(eif0), __high2float(eif1) };
        float eoA[2] = { __low2float(eoo),   __high2float(eoo) };

        float pstash[2];
#pragma unroll
        for (int half = 0; half < 2; half++) {
            int idx = tid + half * 256;
            int b = idx >> 4;
            float eg = ex2f(G[half][2] * L2E2);
            float d1 = 1.0f + eiA[half], d2 = 1.0f + efA[half], d3 = 1.0f + eoA[half];
            float dg = eg + 1.0f;
            float m12 = d1 * d2, m23 = d2 * d3, m13 = d1 * d3;
            float m123 = m12 * d3;
            float r = rcpf(m123 * dg);           // one rcp serves 4 denominators
            float rdg = r * dg;                  // = 1/m123
            float si = rdg * m23, sf = rdg * m13, so = rdg * m12;
            float tg = (eg - 1.0f) * (r * m123); // = (eg-1)/dg
            float c = sf * c_reg[half] + si * tg;
            c_reg[half] = c;
            float ac = fminf(fmaxf(c * L2E2, -60.0f), 60.0f);
            float ec = ex2f(ac);
            float tc = (ec - 1.0f) * rcpf(ec + 1.0f);
            float h = so * tc;
            int jj = idx & 15;
            hdst[(size_t)(b0 + b) * HDIM + j0 + jj] = __float2half_rn(h);
            pstash[half] = h * was_reg[half];
        }

        // ---- publish h(t+1): barrier happens-before + release RED ----
        __syncthreads();
        if (tid == 0)
            asm volatile("red.release.gpu.global.add.u32 [%0], %1;"
                         :: "l"(&g_cnt[grp_p][0]), "r"(1u) : "memory");

        if (t >= SEL_START) {
#pragma unroll
            for (int half = 0; half < 2; half++) {
                int idx = tid + half * 256;
                int b = idx >> 4;
                float p = pstash[half];
                p += __shfl_xor_sync(0xFFFFFFFFu, p, 8);
                p += __shfl_xor_sync(0xFFFFFFFFu, p, 4);
                p += __shfl_xor_sync(0xFFFFFFFFu, p, 2);
                p += __shfl_xor_sync(0xFFFFFFFFu, p, 1);
                if ((lane & 15) == 0)
                    atomicAdd(&out[(b0 + b) * SEL_COUNT + (t - SEL_START)], p);
            }
        }
    }
}

// ---------------- launch ----------------
extern "C" void kernel_launch(void* const* d_in, const int* in_sizes, int n_in,
                              void* d_out, int out_size) {
    (void)in_sizes; (void)n_in; (void)out_size;
    const void*  prob  = d_in[0];
    const float* table = (const float*)d_in[2];
    const float* w_ih  = (const float*)d_in[3];
    const float* w_hh  = (const float*)d_in[4];
    const float* b_ih  = (const float*)d_in[5];
    const float* b_hh  = (const float*)d_in[6];
    const float* w_ans = (const float*)d_in[7];
    const float* b_ans = (const float*)d_in[8];
    const float* h0    = (const float*)d_in[9];
    const float* c0    = (const float*)d_in[10];
    float* out = (float*)d_out;

    static bool inited = false;
    if (!inited) {
        cudaFuncSetAttribute(gemm_pre,     cudaFuncAttributeMaxDynamicSharedMemorySize, GP_SMEM);
        cudaFuncSetAttribute(lstm_persist, cudaFuncAttributeMaxDynamicSharedMemorySize, SMEM_PERSIST);
        inited = true;
    }

    fused_init<<<69, 1024>>>((const int*)prob, h0, out, b_ans);
    prep_all<<<2 * NG + (TSTEPS * BATCH + 1) / 2, 256>>>(prob, table, w_ih, w_hh, b_ih, b_hh);
    gemm_pre<<<dim3(NG / 128, MPAD / 128), 256, GP_SMEM>>>();
    lstm_persist<<<NCTA, 256, SMEM_PERSIST>>>(c0, w_ans, out);
}